// round 6
// baseline (speedup 1.0000x reference)
#include <cuda_runtime.h>
#include <math.h>
#include <stdint.h>

#define BB 8
#define LL 2048
#define DM 512
#define DI 1024
#define NH 16
#define HD 64
#define CD 1056
#define DIP 2096
#define MT (BB*LL)      // 16384 tokens
#define CL 128          // scan chunk length
#define NC (LL/CL)      // 16 chunks
#define NSCAN 256       // 2 dirs * 8 batch * 16 heads

// ---------------- scratch (static device globals; no allocation) ----------------
__device__ float g_zx [2ull*MT*DIP];
__device__ float g_xbc[2ull*MT*CD];
__device__ float g_dt [2ull*MT*NH];
__device__ float g_dA [2ull*MT*NH];
__device__ float g_y  [2ull*MT*DI];
__device__ float g_g  [2ull*MT*DI];          // gated-norm output, tf32-pre-rounded
__device__ float g_P  [(size_t)NSCAN*LL];
__device__ float g_S  [(size_t)NSCAN*NC*HD*16];
__device__ float g_hin[(size_t)NSCAN*NC*HD*16];
__device__ float g_xr [(size_t)MT*DM];       // x, tf32-pre-rounded
__device__ float g_wi [2ull*DIP*DM];         // in_proj weights, rounded
__device__ float g_wo [2ull*DM*DI];          // out_proj weights, rounded

__device__ __forceinline__ float siluf(float v)     { return v / (1.f + expf(-v)); }
__device__ __forceinline__ float softplusf(float v) { return fmaxf(v, 0.f) + log1pf(expf(-fabsf(v))); }
__device__ __forceinline__ uint32_t f2tf32(float f) {
    uint32_t r; asm("cvt.rna.tf32.f32 %0, %1;" : "=r"(r) : "f"(f)); return r;
}
__device__ __forceinline__ float rtf(float f) { return __uint_as_float(f2tf32(f)); }
__device__ __forceinline__ void mma8(float* c, const uint32_t* a, const uint32_t* b) {
    asm volatile(
        "mma.sync.aligned.m16n8k8.row.col.f32.tf32.tf32.f32 "
        "{%0,%1,%2,%3}, {%4,%5,%6,%7}, {%8,%9}, {%0,%1,%2,%3};"
        : "+f"(c[0]), "+f"(c[1]), "+f"(c[2]), "+f"(c[3])
        : "r"(a[0]), "r"(a[1]), "r"(a[2]), "r"(a[3]), "r"(b[0]), "r"(b[1]));
}
__device__ __forceinline__ void cpa16(uint32_t s, const void* g) {
    asm volatile("cp.async.ca.shared.global [%0], [%1], 16;" :: "r"(s), "l"(g));
}
__device__ __forceinline__ void cpa16p(uint32_t s, const void* g, bool pred) {
    int sz = pred ? 16 : 0;
    asm volatile("cp.async.ca.shared.global [%0], [%1], 16, %2;" :: "r"(s), "l"(g), "r"(sz));
}
#define CP_COMMIT() asm volatile("cp.async.commit_group;" ::: "memory")
#define CP_WAIT(n)  asm volatile("cp.async.wait_group %0;" :: "n"(n) : "memory")

// ---------------- tf32 rounding prep ----------------
__global__ __launch_bounds__(256)
void round_k(const float4* __restrict__ s, float4* __restrict__ d, int n4)
{
    int i = blockIdx.x * 256 + threadIdx.x;
    if (i < n4) {
        float4 v = s[i];
        v.x = rtf(v.x); v.y = rtf(v.y); v.z = rtf(v.z); v.w = rtf(v.w);
        d[i] = v;
    }
}

// ============================================================================
// GEMM (BM=128, BN=128, BK=16; 8 warps 2x4, warp tile 64x32), cp.async 3-stage.
// Inputs pre-rounded to tf32 -> fragment loads are raw LDS (no CVT).
// smem: 3 stages x (A 128x20 + B 128x20) floats = 61440 B (dynamic).
// ============================================================================
#define GEMM_SMEM 61440
#define ASM(st,r,k) sA[((st)*128 + (r))*20 + (k)]
#define BSM(st,r,k) sB[((st)*128 + (r))*20 + (k)]

#define GEMM_PROLOGUE \
    extern __shared__ float smp[]; \
    float* sA = smp; \
    float* sB = smp + 3*128*20; \
    const int tid  = threadIdx.x; \
    const int lane = tid & 31; \
    const int wid  = tid >> 5; \
    const int mw   = wid & 1; \
    const int nw   = wid >> 1; \
    const int lr = tid >> 2; \
    const int lc = (tid & 3) << 2; \
    const int g = lane >> 2; \
    const int q = lane & 3; \
    float acc[4][4][4]; \
    _Pragma("unroll") for (int i = 0; i < 4; i++) \
    _Pragma("unroll") for (int j = 0; j < 4; j++) \
    _Pragma("unroll") for (int r = 0; r < 4; r++) acc[i][j][r] = 0.f;

#define GEMM_COMPUTE(cur) \
    _Pragma("unroll") \
    for (int kk = 0; kk < 16; kk += 8) { \
        uint32_t af[4][4], bf[4][2]; \
        _Pragma("unroll") \
        for (int mt = 0; mt < 4; mt++) { \
            int row = mw * 64 + mt * 16 + g; \
            af[mt][0] = __float_as_uint(ASM(cur, row    , kk + q    )); \
            af[mt][1] = __float_as_uint(ASM(cur, row + 8, kk + q    )); \
            af[mt][2] = __float_as_uint(ASM(cur, row    , kk + q + 4)); \
            af[mt][3] = __float_as_uint(ASM(cur, row + 8, kk + q + 4)); \
        } \
        _Pragma("unroll") \
        for (int nt = 0; nt < 4; nt++) { \
            int col = nw * 32 + nt * 8 + g; \
            bf[nt][0] = __float_as_uint(BSM(cur, col, kk + q    )); \
            bf[nt][1] = __float_as_uint(BSM(cur, col, kk + q + 4)); \
        } \
        _Pragma("unroll") \
        for (int mt = 0; mt < 4; mt++) \
        _Pragma("unroll") \
        for (int nt = 0; nt < 4; nt++) \
            mma8(acc[mt][nt], af[mt], bf[nt]); \
    }

#define GEMM_MAINLOOP(T) \
    load_tile(0, 0); CP_COMMIT(); \
    load_tile(1, 1); CP_COMMIT(); \
    load_tile(2, 2); CP_COMMIT(); \
    for (int kt = 0; kt < (T); kt++) { \
        const int cur = kt % 3; \
        CP_WAIT(2); \
        __syncthreads(); \
        GEMM_COMPUTE(cur) \
        __syncthreads(); \
        if (kt + 3 < (T)) load_tile(kt + 3, cur); \
        CP_COMMIT(); \
    }

// ---------------- in_proj: grid (17,128,2); z selects direction ----------------
__global__ void __launch_bounds__(256)
gemm_in(const float* __restrict__ A, const float* __restrict__ Bw,
        float* __restrict__ Cb)
{
    const float* B = Bw + (size_t)blockIdx.z * DIP * DM;
    float* C = Cb + (size_t)blockIdx.z * MT * DIP;
    const int m0 = blockIdx.y * 128, n0 = blockIdx.x * 128;
    const int N = DIP, K = DM;

    GEMM_PROLOGUE

    auto load_tile = [&](int kt, int buf) {
        const int k0 = kt << 4;
#pragma unroll
        for (int i = 0; i < 2; i++) {
            int row = lr + i * 64;
            cpa16((uint32_t)__cvta_generic_to_shared(&ASM(buf, row, lc)),
                  A + (size_t)(m0 + row) * K + k0 + lc);
            cpa16p((uint32_t)__cvta_generic_to_shared(&BSM(buf, row, lc)),
                   B + (size_t)(n0 + row) * K + k0 + lc, (n0 + row) < N);
        }
    };

    GEMM_MAINLOOP(K >> 4)

#pragma unroll
    for (int mt = 0; mt < 4; mt++) {
        int row = m0 + mw * 64 + mt * 16 + g;
#pragma unroll
        for (int nt = 0; nt < 4; nt++) {
            int n = n0 + nw * 32 + nt * 8 + q * 2;
            if (n < N) {
                *(float2*)(C + (size_t)row * DIP + n) =
                    make_float2(acc[mt][nt][0], acc[mt][nt][1]);
                *(float2*)(C + (size_t)(row + 8) * DIP + n) =
                    make_float2(acc[mt][nt][2], acc[mt][nt][3]);
            }
        }
    }
}

// ---------------- out_proj: K-concat of fwd+bwd (K=2048) -> single write ----------------
__global__ void __launch_bounds__(256)
gemm_out(const float* __restrict__ A0, const float* __restrict__ A1,
         const float* __restrict__ Bw, float* __restrict__ C)
{
    const int m0 = blockIdx.y * 128, n0 = blockIdx.x * 128;
    const int K = 2 * DI;

    GEMM_PROLOGUE

    auto load_tile = [&](int kt, int buf) {
        const int k0 = kt << 4;
        const float* Ap; const float* Bp; int kl;
        if (k0 < DI) { Ap = A0; Bp = Bw;                      kl = k0; }
        else         { Ap = A1; Bp = Bw + (size_t)DM * DI;    kl = k0 - DI; }
#pragma unroll
        for (int i = 0; i < 2; i++) {
            int row = lr + i * 64;
            cpa16((uint32_t)__cvta_generic_to_shared(&ASM(buf, row, lc)),
                  Ap + (size_t)(m0 + row) * DI + kl + lc);
            cpa16((uint32_t)__cvta_generic_to_shared(&BSM(buf, row, lc)),
                  Bp + (size_t)(n0 + row) * DI + kl + lc);
        }
    };

    GEMM_MAINLOOP(K >> 4)

#pragma unroll
    for (int mt = 0; mt < 4; mt++) {
        int row = m0 + mw * 64 + mt * 16 + g;
#pragma unroll
        for (int nt = 0; nt < 4; nt++) {
            int n = n0 + nw * 32 + nt * 8 + q * 2;
            *(float2*)(C + (size_t)row * DM + n) =
                make_float2(acc[mt][nt][0], acc[mt][nt][1]);
            *(float2*)(C + (size_t)(row + 8) * DM + n) =
                make_float2(acc[mt][nt][2], acc[mt][nt][3]);
        }
    }
}

// ---------------- depthwise conv(4) + bias + SiLU, 8 outputs per thread ----------------
#define CTT 8
__global__ __launch_bounds__(256)
void conv_silu_k(const float* __restrict__ cwF, const float* __restrict__ cbF,
                 const float* __restrict__ cwB, const float* __restrict__ cbB)
{
    long idx = (long)blockIdx.x * 256 + threadIdx.x;
    int  c  = (int)(idx % CD);
    long q2 = idx / CD;
    int  tg = (int)(q2 & (LL / CTT - 1));
    int  bd = (int)(q2 >> 8);
    int  b  = bd & 7, d = bd >> 3;
    int  t0 = tg * CTT;

    const float* wv = (d == 0 ? cwF : cwB) + c * 4;
    float w0 = wv[0], w1 = wv[1], w2 = wv[2], w3 = wv[3];
    float bias = (d == 0 ? cbF : cbB)[c];
    long rbase = (long)d * MT + (long)b * LL;
    const float* zin = g_zx + rbase * (long)DIP + DI + c;
    float* outp = g_xbc + (rbase + t0) * (long)CD + c;

    float in[CTT + 3];
    if (d == 0) {
#pragma unroll
        for (int j = 0; j < CTT + 3; j++) {
            int tt = t0 - 3 + j;
            in[j] = (tt >= 0) ? zin[(long)tt * DIP] : 0.f;
        }
#pragma unroll
        for (int i = 0; i < CTT; i++) {
            float a = bias;
            a = fmaf(w0, in[i], a); a = fmaf(w1, in[i+1], a);
            a = fmaf(w2, in[i+2], a); a = fmaf(w3, in[i+3], a);
            outp[(long)i * CD] = siluf(a);
        }
    } else {
#pragma unroll
        for (int j = 0; j < CTT + 3; j++) {
            int tt = t0 + j;
            in[j] = (tt < LL) ? zin[(long)tt * DIP] : 0.f;
        }
#pragma unroll
        for (int i = 0; i < CTT; i++) {
            float a = bias;
            a = fmaf(w3, in[i], a); a = fmaf(w2, in[i+1], a);
            a = fmaf(w1, in[i+2], a); a = fmaf(w0, in[i+3], a);
            outp[(long)i * CD] = siluf(a);
        }
    }
}

// ---------------- dt exact fp32, W cached in smem; 64 tokens per block ----------------
__global__ __launch_bounds__(256)
void dadt_k(const float* __restrict__ x,
            const float* __restrict__ ipwF, const float* __restrict__ ipwB,
            const float* __restrict__ dbF,  const float* __restrict__ alF,
            const float* __restrict__ dbB,  const float* __restrict__ alB)
{
    __shared__ float sW[16][512];
    int blk = blockIdx.x;
    int d   = blk >> 8;
    int tb  = blk & 255;
    int tid = threadIdx.x;

    const float* W = (d ? ipwB : ipwF) + (size_t)(DI + CD) * DM;
#pragma unroll
    for (int j = 0; j < 8; j++)
        ((float4*)&sW[0][0])[j * 256 + tid] = ((const float4*)W)[j * 256 + tid];
    __syncthreads();

    int h = tid >> 4, l = tid & 15;
    float db = (d ? dbB : dbF)[h];
    float A  = -expf((d ? alB : alF)[h]);

    for (int tk = 0; tk < 64; tk++) {
        int token = tb * 64 + tk;
        const float4* xr = (const float4*)(x + (size_t)token * DM);
        const float4* wr = (const float4*)&sW[h][0];
        float s = 0.f;
#pragma unroll
        for (int j = 0; j < 8; j++) {
            float4 xv = xr[l + 16 * j];
            float4 wv = wr[l + 16 * j];
            s = fmaf(xv.x, wv.x, s); s = fmaf(xv.y, wv.y, s);
            s = fmaf(xv.z, wv.z, s); s = fmaf(xv.w, wv.w, s);
        }
        s += __shfl_xor_sync(~0u, s, 1);
        s += __shfl_xor_sync(~0u, s, 2);
        s += __shfl_xor_sync(~0u, s, 4);
        s += __shfl_xor_sync(~0u, s, 8);
        if (l == 0) {
            float dt = softplusf(s + db);
            size_t r = (size_t)d * MT + token;
            g_dt[r * NH + h] = dt;
            g_dA[r * NH + h] = expf(dt * A);
        }
    }
}

// ---------------- scan pass 1: chunk scans, 8-step group staging ----------------
__device__ __forceinline__ float ld_bc(long row, int p, int h)
{
    if (p < 32)  return g_xbc[row * (long)CD + DI + p];
    if (p == 32) return g_dt[row * (long)NH + h];
    return g_dA[row * (long)NH + h];
}

__global__ __launch_bounds__(64)
void chunk_scan_k(const float* __restrict__ DpF, const float* __restrict__ DpB)
{
    int blk = blockIdx.x;
    int c   = blk & (NC - 1);
    int sid = blk >> 4;
    int d = sid >> 7, b = (sid >> 4) & 7, h = sid & 15;
    int p = threadIdx.x;

    __shared__ float sBC[2][8][36];   // [buf][step-in-group][B16,C16,dt,dA]
    float hs[16];
#pragma unroll
    for (int n = 0; n < 16; n++) hs[n] = 0.f;
    float dp = (d == 0 ? DpF : DpB)[h];
    long base0 = (long)d * MT + (long)b * LL;
    int s0 = c * CL;

    auto rowof = [&](int s) -> long {
        int t = (d == 0) ? s : (LL - 1 - s);
        return base0 + t;
    };
    auto loadgrp = [&](int gg, int buf) {
#pragma unroll
        for (int it = 0; it < 5; it++) {
            int i = p + it * 64;
            if (i < 272) {
                int j = i / 34, qq = i - j * 34;
                sBC[buf][j][qq] = ld_bc(rowof(s0 + gg * 8 + j), qq, h);
            }
        }
    };

    float xv[8], xn[8];
    loadgrp(0, 0);
#pragma unroll
    for (int j = 0; j < 8; j++)
        xv[j] = g_xbc[rowof(s0 + j) * (long)CD + h * HD + p];
    __syncthreads();

    float P = 1.f;
    for (int gg = 0; gg < 16; gg++) {
        int buf = gg & 1;
        if (gg + 1 < 16) {
            loadgrp(gg + 1, buf ^ 1);
#pragma unroll
            for (int j = 0; j < 8; j++)
                xn[j] = g_xbc[rowof(s0 + (gg + 1) * 8 + j) * (long)CD + h * HD + p];
        }
#pragma unroll
        for (int j = 0; j < 8; j++) {
            float dtv = sBC[buf][j][32], dAv = sBC[buf][j][33];
            float coef = dtv * xv[j];
            float y = 0.f;
#pragma unroll
            for (int n = 0; n < 16; n++) {
                hs[n] = fmaf(hs[n], dAv, coef * sBC[buf][j][n]);
                y = fmaf(hs[n], sBC[buf][j][16 + n], y);
            }
            P *= dAv;
            int s = s0 + gg * 8 + j;
            g_y[rowof(s) * (long)DI + h * HD + p] = fmaf(dp, xv[j], y);
            if (p == 0) g_P[(size_t)sid * LL + s] = P;
        }
        __syncthreads();
#pragma unroll
        for (int j = 0; j < 8; j++) xv[j] = xn[j];
    }

    float* Sp = g_S + (size_t)blk * (HD * 16) + p * 16;
#pragma unroll
    for (int n = 0; n < 16; n++) Sp[n] = hs[n];
}

// ---------------- scan pass 2: serial chunk-state propagation ----------------
__global__ __launch_bounds__(64)
void state_scan_k()
{
    int sid = blockIdx.x;
    int p = threadIdx.x;
    float hs[16];
#pragma unroll
    for (int n = 0; n < 16; n++) hs[n] = 0.f;

    for (int c = 0; c < NC; c++) {
        size_t off = ((size_t)(sid * NC + c)) * (HD * 16) + p * 16;
#pragma unroll
        for (int n = 0; n < 16; n++) g_hin[off + n] = hs[n];
        float Pt = g_P[(size_t)sid * LL + c * CL + CL - 1];
#pragma unroll
        for (int n = 0; n < 16; n++) hs[n] = fmaf(hs[n], Pt, g_S[off + n]);
    }
}

// ---------------- scan pass 3: y[s] += P[s] * (C[s] . h_in) ----------------
__global__ __launch_bounds__(64)
void fixup_k()
{
    int blk = blockIdx.x;
    int cm  = blk % (NC - 1);
    int sid = blk / (NC - 1);
    int c   = cm + 1;
    int d = sid >> 7, b = (sid >> 4) & 7, h = sid & 15;
    int p = threadIdx.x;
    long base0 = (long)d * MT + (long)b * LL;

    size_t off = ((size_t)(sid * NC + c)) * (HD * 16) + p * 16;
    float hin[16];
#pragma unroll
    for (int n = 0; n < 16; n++) hin[n] = g_hin[off + n];

    __shared__ float sC[4][16];
    __shared__ float sP[4];
    int s0 = c * CL;

    for (int i = 0; i < CL; i += 4) {
        {
            int tsub = p >> 4, n = p & 15;
            int s = s0 + i + tsub;
            int t = (d == 0) ? s : (LL - 1 - s);
            sC[tsub][n] = g_xbc[(base0 + t) * (long)CD + DI + 16 + n];
            if (n == 0) sP[tsub] = g_P[(size_t)sid * LL + s];
        }
        __syncthreads();
        float av[4];
#pragma unroll
        for (int j = 0; j < 4; j++) {
            float y = 0.f;
#pragma unroll
            for (int n = 0; n < 16; n++) y = fmaf(hin[n], sC[j][n], y);
            av[j] = y;
        }
#pragma unroll
        for (int j = 0; j < 4; j++) {
            int s = s0 + i + j;
            int t = (d == 0) ? s : (LL - 1 - s);
            long row = base0 + t;
            g_y[row * (long)DI + h * HD + p] += sP[j] * av[j];
        }
        __syncthreads();
    }
}

// ---------------- gated RMSNorm (stores tf32-pre-rounded for gemm_out) ----------------
__global__ __launch_bounds__(256)
void gnorm_k(const float* __restrict__ nwF, const float* __restrict__ nwB)
{
    long r = blockIdx.x;
    int  d = (int)(r / MT);
    const float* nw = (d == 0) ? nwF : nwB;
    const float* yp = g_y  + r * (long)DI;
    const float* zp = g_zx + r * (long)DIP;

    int i0 = threadIdx.x * 4;
    float v[4];
    float ss = 0.f;
#pragma unroll
    for (int j = 0; j < 4; j++) {
        float val = yp[i0 + j] * siluf(zp[i0 + j]);
        v[j] = val;
        ss = fmaf(val, val, ss);
    }
#pragma unroll
    for (int off = 16; off; off >>= 1) ss += __shfl_xor_sync(~0u, ss, off);
    __shared__ float ws[8];
    if ((threadIdx.x & 31) == 0) ws[threadIdx.x >> 5] = ss;
    __syncthreads();
    float tot = ws[0] + ws[1] + ws[2] + ws[3] + ws[4] + ws[5] + ws[6] + ws[7];
    float scale = rsqrtf(tot * (1.f / 1024.f) + 1e-5f);
#pragma unroll
    for (int j = 0; j < 4; j++)
        g_g[r * (long)DI + i0 + j] = rtf(v[j] * scale * nw[i0 + j]);
}

// ---------------- launch ----------------
extern "C" void kernel_launch(void* const* d_in, const int* in_sizes, int n_in,
                              void* d_out, int out_size)
{
    const float* x    = (const float*)d_in[0];
    const float* ipwF = (const float*)d_in[1];
    const float* cwF  = (const float*)d_in[2];
    const float* cbF  = (const float*)d_in[3];
    const float* dbF  = (const float*)d_in[4];
    const float* alF  = (const float*)d_in[5];
    const float* dpF  = (const float*)d_in[6];
    const float* nwF  = (const float*)d_in[7];
    const float* opF  = (const float*)d_in[8];
    const float* ipwB = (const float*)d_in[9];
    const float* cwB  = (const float*)d_in[10];
    const float* cbB  = (const float*)d_in[11];
    const float* dbB  = (const float*)d_in[12];
    const float* alB  = (const float*)d_in[13];
    const float* dpB  = (const float*)d_in[14];
    const float* nwB  = (const float*)d_in[15];
    const float* opB  = (const float*)d_in[16];
    float* out = (float*)d_out;

    float *zx_d, *g_d, *xr_d, *wi_d, *wo_d;
    cudaGetSymbolAddress((void**)&zx_d, g_zx);
    cudaGetSymbolAddress((void**)&g_d,  g_g);
    cudaGetSymbolAddress((void**)&xr_d, g_xr);
    cudaGetSymbolAddress((void**)&wi_d, g_wi);
    cudaGetSymbolAddress((void**)&wo_d, g_wo);

    cudaFuncSetAttribute((const void*)gemm_in,
                         cudaFuncAttributeMaxDynamicSharedMemorySize, GEMM_SMEM);
    cudaFuncSetAttribute((const void*)gemm_out,
                         cudaFuncAttributeMaxDynamicSharedMemorySize, GEMM_SMEM);

    // 0) pre-round GEMM operands to tf32 (numerics identical to per-fragment CVT)
    {
        int n4x = MT * DM / 4;
        round_k<<<(n4x + 255) / 256, 256>>>((const float4*)x, (float4*)xr_d, n4x);
        int n4i = DIP * DM / 4;
        round_k<<<(n4i + 255) / 256, 256>>>((const float4*)ipwF, (float4*)wi_d, n4i);
        round_k<<<(n4i + 255) / 256, 256>>>((const float4*)ipwB, (float4*)(wi_d + (size_t)DIP * DM), n4i);
        int n4o = DM * DI / 4;
        round_k<<<(n4o + 255) / 256, 256>>>((const float4*)opF, (float4*)wo_d, n4o);
        round_k<<<(n4o + 255) / 256, 256>>>((const float4*)opB, (float4*)(wo_d + (size_t)DM * DI), n4o);
    }

    // 1) in_proj both directions (grid.z = dir), 3-stage cp.async tf32 MMA
    gemm_in<<<dim3(17, 128, 2), 256, GEMM_SMEM>>>(xr_d, wi_d, zx_d);

    // 2) depthwise conv + silu
    {
        long total = 2L * 8 * (LL / CTT) * CD;
        conv_silu_k<<<(unsigned)(total / 256), 256>>>(cwF, cbF, cwB, cbB);
    }

    // 3) dt / dA (exact fp32, W in smem)
    dadt_k<<<512, 256>>>(x, ipwF, ipwB, dbF, alF, dbB, alB);

    // 4) chunked selective scan
    chunk_scan_k<<<NSCAN * NC, 64>>>(dpF, dpB);
    state_scan_k<<<NSCAN, 64>>>();
    fixup_k<<<NSCAN * (NC - 1), 64>>>();

    // 5) gated RMSNorm
    gnorm_k<<<2 * MT, 256>>>(nwF, nwB);

    // 6) out_proj: single GEMM, K-concat fwd+bwd
    gemm_out<<<dim3(4, 128), 256, GEMM_SMEM>>>(g_d, g_d + (size_t)MT * DI, wo_d, out);
}

// round 7
// speedup vs baseline: 1.1141x; 1.1141x over previous
#include <cuda_runtime.h>
#include <math.h>
#include <stdint.h>

#define BB 8
#define LL 2048
#define DM 512
#define DI 1024
#define NH 16
#define HD 64
#define CD 1056
#define DIP 2096
#define MT (BB*LL)      // 16384 tokens
#define CL 128          // scan chunk length
#define NC (LL/CL)      // 16 chunks
#define NSCAN 256       // 2 dirs * 8 batch * 16 heads

// ---------------- scratch (static device globals; no allocation) ----------------
__device__ float g_zx [2ull*MT*DIP];
__device__ float g_xbc[2ull*MT*CD];
__device__ float g_dt [2ull*MT*NH];
__device__ float g_dA [2ull*MT*NH];
__device__ float g_y  [2ull*MT*DI];
__device__ float g_g  [2ull*MT*DI];
__device__ float g_P  [(size_t)NSCAN*LL];
__device__ float g_S  [(size_t)NSCAN*NC*HD*16];
__device__ float g_hin[(size_t)NSCAN*NC*HD*16];

__device__ __forceinline__ float siluf(float v)     { return v / (1.f + expf(-v)); }
__device__ __forceinline__ float softplusf(float v) { return fmaxf(v, 0.f) + log1pf(expf(-fabsf(v))); }
__device__ __forceinline__ uint32_t f2tf32(float f) {
    uint32_t r; asm("cvt.rna.tf32.f32 %0, %1;" : "=r"(r) : "f"(f)); return r;
}
__device__ __forceinline__ void mma8(float* c, const uint32_t* a, const uint32_t* b) {
    asm volatile(
        "mma.sync.aligned.m16n8k8.row.col.f32.tf32.tf32.f32 "
        "{%0,%1,%2,%3}, {%4,%5,%6,%7}, {%8,%9}, {%0,%1,%2,%3};"
        : "+f"(c[0]), "+f"(c[1]), "+f"(c[2]), "+f"(c[3])
        : "r"(a[0]), "r"(a[1]), "r"(a[2]), "r"(a[3]), "r"(b[0]), "r"(b[1]));
}
__device__ __forceinline__ void cpa16(const void* sp, const void* g) {
    uint32_t s = (uint32_t)__cvta_generic_to_shared(sp);
    asm volatile("cp.async.cg.shared.global [%0], [%1], 16;" :: "r"(s), "l"(g));
}
__device__ __forceinline__ void cpa16p(const void* sp, const void* g, bool pred) {
    uint32_t s = (uint32_t)__cvta_generic_to_shared(sp);
    int sz = pred ? 16 : 0;
    asm volatile("cp.async.cg.shared.global [%0], [%1], 16, %2;" :: "r"(s), "l"(g), "r"(sz));
}
#define CP_COMMIT() asm volatile("cp.async.commit_group;" ::: "memory")
#define CP_WAIT(n)  asm volatile("cp.async.wait_group %0;" :: "n"(n) : "memory")

// ============================================================================
// GEMM (BM=128, BN=128, BK=32; 8 warps 2x4, warp tile 64x32), cp.async 2-stage.
// smem [row][36] floats per stage: conflict-free fragment reads.
// Dynamic smem: 2 stages x (A 128x36 + B 128x36) x 4B = 73728 B.
// ============================================================================
#define GEMM_SMEM 73728
#define ASM(st,r,k) sA[((st)*128 + (r))*36 + (k)]
#define BSM(st,r,k) sB[((st)*128 + (r))*36 + (k)]

#define GEMM_PROLOGUE \
    extern __shared__ float smp[]; \
    float* sA = smp; \
    float* sB = smp + 2*128*36; \
    const int tid  = threadIdx.x; \
    const int lane = tid & 31; \
    const int wid  = tid >> 5; \
    const int mw   = wid & 1; \
    const int nw   = wid >> 1; \
    const int g = lane >> 2; \
    const int q = lane & 3; \
    float acc[4][4][4]; \
    _Pragma("unroll") for (int i = 0; i < 4; i++) \
    _Pragma("unroll") for (int j = 0; j < 4; j++) \
    _Pragma("unroll") for (int r = 0; r < 4; r++) acc[i][j][r] = 0.f;

#define GEMM_COMPUTE(cur) \
    _Pragma("unroll") \
    for (int kk = 0; kk < 32; kk += 8) { \
        uint32_t af[4][4], bf[4][2]; \
        _Pragma("unroll") \
        for (int mt = 0; mt < 4; mt++) { \
            int row = mw * 64 + mt * 16 + g; \
            af[mt][0] = f2tf32(ASM(cur, row    , kk + q    )); \
            af[mt][1] = f2tf32(ASM(cur, row + 8, kk + q    )); \
            af[mt][2] = f2tf32(ASM(cur, row    , kk + q + 4)); \
            af[mt][3] = f2tf32(ASM(cur, row + 8, kk + q + 4)); \
        } \
        _Pragma("unroll") \
        for (int nt = 0; nt < 4; nt++) { \
            int col = nw * 32 + nt * 8 + g; \
            bf[nt][0] = f2tf32(BSM(cur, col, kk + q    )); \
            bf[nt][1] = f2tf32(BSM(cur, col, kk + q + 4)); \
        } \
        _Pragma("unroll") \
        for (int mt = 0; mt < 4; mt++) \
        _Pragma("unroll") \
        for (int nt = 0; nt < 4; nt++) \
            mma8(acc[mt][nt], af[mt], bf[nt]); \
    }

#define GEMM_MAINLOOP(T) \
    load_tile(0, 0); CP_COMMIT(); \
    load_tile(1, 1); CP_COMMIT(); \
    for (int kt = 0; kt < (T); kt++) { \
        const int cur = kt & 1; \
        if (kt + 1 < (T)) { CP_WAIT(1); } else { CP_WAIT(0); } \
        __syncthreads(); \
        GEMM_COMPUTE(cur) \
        __syncthreads(); \
        if (kt + 2 < (T)) { load_tile(kt + 2, cur); CP_COMMIT(); } \
    }

// ---------------- in_proj: grid (17,128,2); z selects direction ----------------
__global__ void __launch_bounds__(256, 2)
gemm_in(const float* __restrict__ A, const float* __restrict__ B0,
        const float* __restrict__ B1, float* __restrict__ Cb)
{
    const float* B = blockIdx.z ? B1 : B0;
    float* C = Cb + (size_t)blockIdx.z * MT * DIP;
    const int m0 = blockIdx.y * 128, n0 = blockIdx.x * 128;
    const int N = DIP, K = DM;

    GEMM_PROLOGUE

    auto load_tile = [&](int kt, int buf) {
        const int k0 = kt << 5;
#pragma unroll
        for (int i = 0; i < 4; i++) {
            int id  = tid + (i << 8);
            int row = id >> 3;
            int ce  = (id & 7) << 2;
            cpa16(&ASM(buf, row, ce), A + (size_t)(m0 + row) * K + k0 + ce);
            cpa16p(&BSM(buf, row, ce), B + (size_t)(n0 + row) * K + k0 + ce,
                   (n0 + row) < N);
        }
    };

    GEMM_MAINLOOP(K >> 5)

#pragma unroll
    for (int mt = 0; mt < 4; mt++) {
        int row = m0 + mw * 64 + mt * 16 + g;
#pragma unroll
        for (int nt = 0; nt < 4; nt++) {
            int n = n0 + nw * 32 + nt * 8 + q * 2;
            if (n < N) {
                *(float2*)(C + (size_t)row * DIP + n) =
                    make_float2(acc[mt][nt][0], acc[mt][nt][1]);
                *(float2*)(C + (size_t)(row + 8) * DIP + n) =
                    make_float2(acc[mt][nt][2], acc[mt][nt][3]);
            }
        }
    }
}

// ---------------- out_proj: K-concat of fwd+bwd (K=2048) -> single write ----------------
__global__ void __launch_bounds__(256, 2)
gemm_out(const float* __restrict__ A0, const float* __restrict__ A1,
         const float* __restrict__ B0, const float* __restrict__ B1,
         float* __restrict__ C)
{
    const int m0 = blockIdx.y * 128, n0 = blockIdx.x * 128;
    const int K = 2 * DI;

    GEMM_PROLOGUE

    auto load_tile = [&](int kt, int buf) {
        const int k0 = kt << 5;
        const float* Ap; const float* Bp; int kl;
        if (k0 < DI) { Ap = A0; Bp = B0; kl = k0; }
        else         { Ap = A1; Bp = B1; kl = k0 - DI; }
#pragma unroll
        for (int i = 0; i < 4; i++) {
            int id  = tid + (i << 8);
            int row = id >> 3;
            int ce  = (id & 7) << 2;
            cpa16(&ASM(buf, row, ce), Ap + (size_t)(m0 + row) * DI + kl + ce);
            cpa16(&BSM(buf, row, ce), Bp + (size_t)(n0 + row) * DI + kl + ce);
        }
    };

    GEMM_MAINLOOP(K >> 5)

#pragma unroll
    for (int mt = 0; mt < 4; mt++) {
        int row = m0 + mw * 64 + mt * 16 + g;
#pragma unroll
        for (int nt = 0; nt < 4; nt++) {
            int n = n0 + nw * 32 + nt * 8 + q * 2;
            *(float2*)(C + (size_t)row * DM + n) =
                make_float2(acc[mt][nt][0], acc[mt][nt][1]);
            *(float2*)(C + (size_t)(row + 8) * DM + n) =
                make_float2(acc[mt][nt][2], acc[mt][nt][3]);
        }
    }
}

// ---------------- depthwise conv(4) + bias + SiLU, 8 outputs per thread ----------------
#define CTT 8
__global__ __launch_bounds__(256)
void conv_silu_k(const float* __restrict__ cwF, const float* __restrict__ cbF,
                 const float* __restrict__ cwB, const float* __restrict__ cbB)
{
    long idx = (long)blockIdx.x * 256 + threadIdx.x;
    int  c  = (int)(idx % CD);
    long q2 = idx / CD;
    int  tg = (int)(q2 & (LL / CTT - 1));
    int  bd = (int)(q2 >> 8);
    int  b  = bd & 7, d = bd >> 3;
    int  t0 = tg * CTT;

    const float* wv = (d == 0 ? cwF : cwB) + c * 4;
    float w0 = wv[0], w1 = wv[1], w2 = wv[2], w3 = wv[3];
    float bias = (d == 0 ? cbF : cbB)[c];
    long rbase = (long)d * MT + (long)b * LL;
    const float* zin = g_zx + rbase * (long)DIP + DI + c;
    float* outp = g_xbc + (rbase + t0) * (long)CD + c;

    float in[CTT + 3];
    if (d == 0) {
#pragma unroll
        for (int j = 0; j < CTT + 3; j++) {
            int tt = t0 - 3 + j;
            in[j] = (tt >= 0) ? zin[(long)tt * DIP] : 0.f;
        }
#pragma unroll
        for (int i = 0; i < CTT; i++) {
            float a = bias;
            a = fmaf(w0, in[i], a); a = fmaf(w1, in[i+1], a);
            a = fmaf(w2, in[i+2], a); a = fmaf(w3, in[i+3], a);
            outp[(long)i * CD] = siluf(a);
        }
    } else {
#pragma unroll
        for (int j = 0; j < CTT + 3; j++) {
            int tt = t0 + j;
            in[j] = (tt < LL) ? zin[(long)tt * DIP] : 0.f;
        }
#pragma unroll
        for (int i = 0; i < CTT; i++) {
            float a = bias;
            a = fmaf(w3, in[i], a); a = fmaf(w2, in[i+1], a);
            a = fmaf(w1, in[i+2], a); a = fmaf(w0, in[i+3], a);
            outp[(long)i * CD] = siluf(a);
        }
    }
}

// ---------------- dt exact fp32, W cached in smem; 64 tokens per block ----------------
__global__ __launch_bounds__(256)
void dadt_k(const float* __restrict__ x,
            const float* __restrict__ ipwF, const float* __restrict__ ipwB,
            const float* __restrict__ dbF,  const float* __restrict__ alF,
            const float* __restrict__ dbB,  const float* __restrict__ alB)
{
    __shared__ float sW[16][512];
    int blk = blockIdx.x;
    int d   = blk >> 8;
    int tb  = blk & 255;
    int tid = threadIdx.x;

    const float* W = (d ? ipwB : ipwF) + (size_t)(DI + CD) * DM;
#pragma unroll
    for (int j = 0; j < 8; j++)
        ((float4*)&sW[0][0])[j * 256 + tid] = ((const float4*)W)[j * 256 + tid];
    __syncthreads();

    int h = tid >> 4, l = tid & 15;
    float db = (d ? dbB : dbF)[h];
    float A  = -expf((d ? alB : alF)[h]);

    for (int tk = 0; tk < 64; tk++) {
        int token = tb * 64 + tk;
        const float4* xr = (const float4*)(x + (size_t)token * DM);
        const float4* wr = (const float4*)&sW[h][0];
        float s = 0.f;
#pragma unroll
        for (int j = 0; j < 8; j++) {
            float4 xv = xr[l + 16 * j];
            float4 wv = wr[l + 16 * j];
            s = fmaf(xv.x, wv.x, s); s = fmaf(xv.y, wv.y, s);
            s = fmaf(xv.z, wv.z, s); s = fmaf(xv.w, wv.w, s);
        }
        s += __shfl_xor_sync(~0u, s, 1);
        s += __shfl_xor_sync(~0u, s, 2);
        s += __shfl_xor_sync(~0u, s, 4);
        s += __shfl_xor_sync(~0u, s, 8);
        if (l == 0) {
            float dt = softplusf(s + db);
            size_t r = (size_t)d * MT + token;
            g_dt[r * NH + h] = dt;
            g_dA[r * NH + h] = expf(dt * A);
        }
    }
}

// ---------------- scan pass 1: chunk scans, 8-step group staging ----------------
__device__ __forceinline__ float ld_bc(long row, int p, int h)
{
    if (p < 32)  return g_xbc[row * (long)CD + DI + p];
    if (p == 32) return g_dt[row * (long)NH + h];
    return g_dA[row * (long)NH + h];
}

__global__ __launch_bounds__(64)
void chunk_scan_k(const float* __restrict__ DpF, const float* __restrict__ DpB)
{
    int blk = blockIdx.x;
    int c   = blk & (NC - 1);
    int sid = blk >> 4;
    int d = sid >> 7, b = (sid >> 4) & 7, h = sid & 15;
    int p = threadIdx.x;

    __shared__ float sBC[2][8][36];
    float hs[16];
#pragma unroll
    for (int n = 0; n < 16; n++) hs[n] = 0.f;
    float dp = (d == 0 ? DpF : DpB)[h];
    long base0 = (long)d * MT + (long)b * LL;
    int s0 = c * CL;

    auto rowof = [&](int s) -> long {
        int t = (d == 0) ? s : (LL - 1 - s);
        return base0 + t;
    };
    auto loadgrp = [&](int gg, int buf) {
#pragma unroll
        for (int it = 0; it < 5; it++) {
            int i = p + it * 64;
            if (i < 272) {
                int j = i / 34, qq = i - j * 34;
                sBC[buf][j][qq] = ld_bc(rowof(s0 + gg * 8 + j), qq, h);
            }
        }
    };

    float xv[8], xn[8];
    loadgrp(0, 0);
#pragma unroll
    for (int j = 0; j < 8; j++)
        xv[j] = g_xbc[rowof(s0 + j) * (long)CD + h * HD + p];
    __syncthreads();

    float P = 1.f;
    for (int gg = 0; gg < 16; gg++) {
        int buf = gg & 1;
        if (gg + 1 < 16) {
            loadgrp(gg + 1, buf ^ 1);
#pragma unroll
            for (int j = 0; j < 8; j++)
                xn[j] = g_xbc[rowof(s0 + (gg + 1) * 8 + j) * (long)CD + h * HD + p];
        }
#pragma unroll
        for (int j = 0; j < 8; j++) {
            float dtv = sBC[buf][j][32], dAv = sBC[buf][j][33];
            float coef = dtv * xv[j];
            float y = 0.f;
#pragma unroll
            for (int n = 0; n < 16; n++) {
                hs[n] = fmaf(hs[n], dAv, coef * sBC[buf][j][n]);
                y = fmaf(hs[n], sBC[buf][j][16 + n], y);
            }
            P *= dAv;
            int s = s0 + gg * 8 + j;
            g_y[rowof(s) * (long)DI + h * HD + p] = fmaf(dp, xv[j], y);
            if (p == 0) g_P[(size_t)sid * LL + s] = P;
        }
        __syncthreads();
#pragma unroll
        for (int j = 0; j < 8; j++) xv[j] = xn[j];
    }

    float* Sp = g_S + (size_t)blk * (HD * 16) + p * 16;
#pragma unroll
    for (int n = 0; n < 16; n++) Sp[n] = hs[n];
}

// ---------------- scan pass 2: serial chunk-state propagation ----------------
__global__ __launch_bounds__(64)
void state_scan_k()
{
    int sid = blockIdx.x;
    int p = threadIdx.x;
    float hs[16];
#pragma unroll
    for (int n = 0; n < 16; n++) hs[n] = 0.f;

    for (int c = 0; c < NC; c++) {
        size_t off = ((size_t)(sid * NC + c)) * (HD * 16) + p * 16;
#pragma unroll
        for (int n = 0; n < 16; n++) g_hin[off + n] = hs[n];
        float Pt = g_P[(size_t)sid * LL + c * CL + CL - 1];
#pragma unroll
        for (int n = 0; n < 16; n++) hs[n] = fmaf(hs[n], Pt, g_S[off + n]);
    }
}

// ---------------- scan pass 3: y[s] += P[s] * (C[s] . h_in) ----------------
__global__ __launch_bounds__(64)
void fixup_k()
{
    int blk = blockIdx.x;
    int cm  = blk % (NC - 1);
    int sid = blk / (NC - 1);
    int c   = cm + 1;
    int d = sid >> 7, b = (sid >> 4) & 7, h = sid & 15;
    int p = threadIdx.x;
    long base0 = (long)d * MT + (long)b * LL;

    size_t off = ((size_t)(sid * NC + c)) * (HD * 16) + p * 16;
    float hin[16];
#pragma unroll
    for (int n = 0; n < 16; n++) hin[n] = g_hin[off + n];

    __shared__ float sC[4][16];
    __shared__ float sP[4];
    int s0 = c * CL;

    for (int i = 0; i < CL; i += 4) {
        {
            int tsub = p >> 4, n = p & 15;
            int s = s0 + i + tsub;
            int t = (d == 0) ? s : (LL - 1 - s);
            sC[tsub][n] = g_xbc[(base0 + t) * (long)CD + DI + 16 + n];
            if (n == 0) sP[tsub] = g_P[(size_t)sid * LL + s];
        }
        __syncthreads();
        float av[4];
#pragma unroll
        for (int j = 0; j < 4; j++) {
            float y = 0.f;
#pragma unroll
            for (int n = 0; n < 16; n++) y = fmaf(hin[n], sC[j][n], y);
            av[j] = y;
        }
#pragma unroll
        for (int j = 0; j < 4; j++) {
            int s = s0 + i + j;
            int t = (d == 0) ? s : (LL - 1 - s);
            long row = base0 + t;
            g_y[row * (long)DI + h * HD + p] += sP[j] * av[j];
        }
        __syncthreads();
    }
}

// ---------------- gated RMSNorm ----------------
__global__ __launch_bounds__(256)
void gnorm_k(const float* __restrict__ nwF, const float* __restrict__ nwB)
{
    long r = blockIdx.x;
    int  d = (int)(r / MT);
    const float* nw = (d == 0) ? nwF : nwB;
    const float* yp = g_y  + r * (long)DI;
    const float* zp = g_zx + r * (long)DIP;

    int i0 = threadIdx.x * 4;
    float v[4];
    float ss = 0.f;
#pragma unroll
    for (int j = 0; j < 4; j++) {
        float val = yp[i0 + j] * siluf(zp[i0 + j]);
        v[j] = val;
        ss = fmaf(val, val, ss);
    }
#pragma unroll
    for (int off = 16; off; off >>= 1) ss += __shfl_xor_sync(~0u, ss, off);
    __shared__ float ws[8];
    if ((threadIdx.x & 31) == 0) ws[threadIdx.x >> 5] = ss;
    __syncthreads();
    float tot = ws[0] + ws[1] + ws[2] + ws[3] + ws[4] + ws[5] + ws[6] + ws[7];
    float scale = rsqrtf(tot * (1.f / 1024.f) + 1e-5f);
#pragma unroll
    for (int j = 0; j < 4; j++)
        g_g[r * (long)DI + i0 + j] = v[j] * scale * nw[i0 + j];
}

// ---------------- launch ----------------
extern "C" void kernel_launch(void* const* d_in, const int* in_sizes, int n_in,
                              void* d_out, int out_size)
{
    const float* x    = (const float*)d_in[0];
    const float* ipwF = (const float*)d_in[1];
    const float* cwF  = (const float*)d_in[2];
    const float* cbF  = (const float*)d_in[3];
    const float* dbF  = (const float*)d_in[4];
    const float* alF  = (const float*)d_in[5];
    const float* dpF  = (const float*)d_in[6];
    const float* nwF  = (const float*)d_in[7];
    const float* opF  = (const float*)d_in[8];
    const float* ipwB = (const float*)d_in[9];
    const float* cwB  = (const float*)d_in[10];
    const float* cbB  = (const float*)d_in[11];
    const float* dbB  = (const float*)d_in[12];
    const float* alB  = (const float*)d_in[13];
    const float* dpB  = (const float*)d_in[14];
    const float* nwB  = (const float*)d_in[15];
    const float* opB  = (const float*)d_in[16];
    float* out = (float*)d_out;

    float *zx_d, *g_d;
    cudaGetSymbolAddress((void**)&zx_d, g_zx);
    cudaGetSymbolAddress((void**)&g_d,  g_g);

    cudaFuncSetAttribute((const void*)gemm_in,
                         cudaFuncAttributeMaxDynamicSharedMemorySize, GEMM_SMEM);
    cudaFuncSetAttribute((const void*)gemm_out,
                         cudaFuncAttributeMaxDynamicSharedMemorySize, GEMM_SMEM);

    // 1) in_proj both directions (grid.z = dir), BK=32 cp.async tf32 MMA
    gemm_in<<<dim3(17, 128, 2), 256, GEMM_SMEM>>>(x, ipwF, ipwB, zx_d);

    // 2) depthwise conv + silu
    {
        long total = 2L * 8 * (LL / CTT) * CD;
        conv_silu_k<<<(unsigned)(total / 256), 256>>>(cwF, cbF, cwB, cbB);
    }

    // 3) dt / dA (exact fp32, W in smem)
    dadt_k<<<512, 256>>>(x, ipwF, ipwB, dbF, alF, dbB, alB);

    // 4) chunked selective scan
    chunk_scan_k<<<NSCAN * NC, 64>>>(dpF, dpB);
    state_scan_k<<<NSCAN, 64>>>();
    fixup_k<<<NSCAN * (NC - 1), 64>>>();

    // 5) gated RMSNorm
    gnorm_k<<<2 * MT, 256>>>(nwF, nwB);

    // 6) out_proj: single GEMM, K-concat fwd+bwd
    gemm_out<<<dim3(4, 128), 256, GEMM_SMEM>>>(g_d, g_d + (size_t)MT * DI, opF, opB, out);
}